// round 16
// baseline (speedup 1.0000x reference)
#include <cuda_runtime.h>
#include <cuda_bf16.h>
#include <math.h>
#include <stdint.h>

#define B_    2
#define S_    2048
#define D_    1024
#define H_    16
#define HD_   64
#define ROWS  (B_ * S_)   /* 4096 */
#define TSTR  36          /* u32 stride of packed bf16 V smem tiles */
#define KS    68          /* float stride of fp32 K smem tile */

// Scratch (allocation-free rule: __device__ globals)
__device__ float g_q[ROWS * D_];
__device__ float g_k[ROWS * D_];
__device__ float g_v[ROWS * D_];
__device__ float g_ctx[ROWS * D_];
__device__ float g_x[ROWS * D_];
__device__ float g_wq[D_ * D_];   // tf32-rounded [K][N] (natural layout)
__device__ float g_wk[D_ * D_];
__device__ float g_wv[D_ * D_];
__device__ float g_wo[D_ * D_];
__device__ float g_cos[S_ * 32];
__device__ float g_sin[S_ * 32];
// attention operands: Q/K tf32-rounded fp32 (post-rope), V packed bf16 hi/lo
__device__ float g_qt[ROWS * D_];
__device__ float g_kt[ROWS * D_];
__device__ uint32_t g_vthi[B_ * H_ * HD_ * (S_ / 2)];
__device__ uint32_t g_vtlo[B_ * H_ * HD_ * (S_ / 2)];

// ---------------------------------------------------------------------------
// helpers (portable PTX, no 'a'-suffix features)
// ---------------------------------------------------------------------------
__device__ __forceinline__ uint32_t f2tf32(float x) {
    uint32_t r;
    asm("cvt.rna.tf32.f32 %0, %1;" : "=r"(r) : "f"(x));
    return r;
}

__device__ __forceinline__ void mma_tf32(float* d, const uint32_t* a,
                                         const uint32_t* b) {
    asm volatile(
        "mma.sync.aligned.m16n8k8.row.col.f32.tf32.tf32.f32 "
        "{%0,%1,%2,%3}, {%4,%5,%6,%7}, {%8,%9}, {%0,%1,%2,%3};"
        : "+f"(d[0]), "+f"(d[1]), "+f"(d[2]), "+f"(d[3])
        : "r"(a[0]), "r"(a[1]), "r"(a[2]), "r"(a[3]),
          "r"(b[0]), "r"(b[1]));
}

__device__ __forceinline__ void mma_bf16(float* d, const uint32_t* a,
                                         const uint32_t* b) {
    asm volatile(
        "mma.sync.aligned.m16n8k16.row.col.f32.bf16.bf16.f32 "
        "{%0,%1,%2,%3}, {%4,%5,%6,%7}, {%8,%9}, {%0,%1,%2,%3};"
        : "+f"(d[0]), "+f"(d[1]), "+f"(d[2]), "+f"(d[3])
        : "r"(a[0]), "r"(a[1]), "r"(a[2]), "r"(a[3]),
          "r"(b[0]), "r"(b[1]));
}

__device__ __forceinline__ void ldsm_x4(uint32_t* r, uint32_t a) {
    asm volatile(
        "ldmatrix.sync.aligned.m8n8.x4.shared.b16 {%0,%1,%2,%3}, [%4];"
        : "=r"(r[0]), "=r"(r[1]), "=r"(r[2]), "=r"(r[3]) : "r"(a));
}

__device__ __forceinline__ void split_bf16x2(float a, float b,
                                             uint32_t& hi, uint32_t& lo) {
    __nv_bfloat16 ha = __float2bfloat16_rn(a);
    __nv_bfloat16 hb = __float2bfloat16_rn(b);
    __nv_bfloat162 h; h.x = ha; h.y = hb;
    hi = *reinterpret_cast<uint32_t*>(&h);
    float ra = a - __bfloat162float(ha);
    float rb = b - __bfloat162float(hb);
    __nv_bfloat162 l = __floats2bfloat162_rn(ra, rb);
    lo = *reinterpret_cast<uint32_t*>(&l);
}

__device__ __forceinline__ uint32_t smem_u32(const void* p) {
    uint32_t a;
    asm("{ .reg .u64 t; cvta.to.shared.u64 t, %1; cvt.u32.u64 %0, t; }"
        : "=r"(a) : "l"(p));
    return a;
}
#define CP_ASYNC16(dst_u32, src_ptr) \
    asm volatile("cp.async.cg.shared.global [%0], [%1], 16;" \
                 :: "r"(dst_u32), "l"(src_ptr))
#define CP_COMMIT() asm volatile("cp.async.commit_group;" ::: "memory")
#define CP_WAIT(N)  asm volatile("cp.async.wait_group %0;" :: "n"(N) : "memory")

// ---------------------------------------------------------------------------
// Launch 1: prep_all — round x + 4 weights to tf32, rope tables. Partitioned
// 1D grid so attn_kernel lands as the 4th launch (ncu captures #4).
// ---------------------------------------------------------------------------
#define XBLK   (ROWS * D_ / 4 / 256)   /* 4096 */
#define WBLK   (D_ * D_ / 4 / 256)     /* 1024 */
#define RTBLK  (S_ * 32 / 256)         /* 256 */
#define PREP_BLOCKS (XBLK + 4 * WBLK + RTBLK)

__global__ void prep_all_kernel(
    const float* __restrict__ x,
    const float* __restrict__ Wq, const float* __restrict__ Wk,
    const float* __restrict__ Wv, const float* __restrict__ Wo)
{
    int bid = blockIdx.x;
    if (bid >= XBLK + 4 * WBLK) {
        int idx = (bid - XBLK - 4 * WBLK) * 256 + threadIdx.x;
        int i = idx & 31, pos = idx >> 5;
        double invf_d = exp(-log(10000.0) * (double)(2 * i) / (double)HD_);
        float ang = (float)pos * (float)invf_d;
        double sd, cd;
        sincos((double)ang, &sd, &cd);
        g_cos[pos * 32 + i] = (float)cd;
        g_sin[pos * 32 + i] = (float)sd;
        return;
    }
    const float* s;
    float* d;
    int i;
    if (bid < XBLK) {
        s = x; d = g_x; i = (bid * 256 + threadIdx.x) * 4;
    } else {
        int z  = (bid - XBLK) / WBLK;
        int lb = (bid - XBLK) % WBLK;
        s = (z == 0) ? Wq : (z == 1) ? Wk : (z == 2) ? Wv : Wo;
        d = (z == 0) ? g_wq : (z == 1) ? g_wk : (z == 2) ? g_wv : g_wo;
        i = (lb * 256 + threadIdx.x) * 4;
    }
    float4 v = *(const float4*)(s + i);
    v.x = __uint_as_float(f2tf32(v.x));
    v.y = __uint_as_float(f2tf32(v.y));
    v.z = __uint_as_float(f2tf32(v.z));
    v.w = __uint_as_float(f2tf32(v.w));
    *(float4*)(d + i) = v;
}

// ---------------------------------------------------------------------------
// HMMA tf32 GEMM body — EXACT round-14 configuration (best measured):
// 3-stage cp.async, ONE barrier per chunk, 2 CTAs/SM, A-frags via ldmatrix,
// B [k][n] scalar fragment loads. ASTR 40 / BSTR 136.
// ---------------------------------------------------------------------------
#define ASTR 40
#define BSTR 136
#define AS_F (128 * ASTR)
#define BS_F (32 * BSTR)
#define GEMM_SMEM (3 * (AS_F + BS_F) * 4)   /* 113664 B */

__device__ __forceinline__ void gemm_body(
    const float* __restrict__ A, const float* __restrict__ W,
    float* __restrict__ C, int M, int N, int K, float* sh)
{
    float* Asb[3] = {sh, sh + AS_F, sh + 2 * AS_F};
    float* Bsb[3] = {sh + 3 * AS_F, sh + 3 * AS_F + BS_F, sh + 3 * AS_F + 2 * BS_F};

    const int tid  = threadIdx.x;
    const int wid  = tid >> 5;
    const int lane = tid & 31;
    const int bm   = blockIdx.y * 128;
    const int bn   = blockIdx.x * 128;
    const int wm   = wid >> 2;
    const int wn   = wid & 3;
    const int lr   = lane >> 2;
    const int lc   = lane & 3;
    const int g    = lane >> 3;
    const int ri   = lane & 7;
    const int alr  = wm * 64 + ((g & 1) << 3) + ri;  // + 16*i
    const int alc  = (g >> 1) << 2;                  // + 8*s

    const int a_r  = tid >> 1;
    const int a_c  = (tid & 1) * 16;
    const int b_r  = tid >> 3;
    const int b_c  = (tid & 7) * 4;

    const float* Arow = A + (size_t)(bm + a_r) * K + a_c;
    const float* Wrow0 = W + (size_t)b_r * N + bn + b_c;

    float acc[4][4][4];
#pragma unroll
    for (int i = 0; i < 4; i++)
#pragma unroll
        for (int j = 0; j < 4; j++)
#pragma unroll
            for (int t = 0; t < 4; t++) acc[i][j][t] = 0.f;

    auto issue_chunk = [&](int c, int buf) {
        uint32_t ad = smem_u32(Asb[buf] + a_r * ASTR + a_c);
        const float* ap = Arow + c * 32;
#pragma unroll
        for (int f = 0; f < 4; f++)
            CP_ASYNC16(ad + f * 16, ap + f * 4);
        uint32_t bd = smem_u32(Bsb[buf] + b_r * BSTR + b_c);
        const float* bp = Wrow0 + (size_t)(c * 32) * N;
#pragma unroll
        for (int f = 0; f < 4; f++)
            CP_ASYNC16(bd + f * 128, bp + f * 32);
        CP_COMMIT();
    };

    const int CHUNKS = K / 32;
    issue_chunk(0, 0);
    issue_chunk(1, 1);

    int buf = 0;
    for (int c = 0; c < CHUNKS; c++) {
        if (c + 1 < CHUNKS) { CP_WAIT(1); } else { CP_WAIT(0); }
        __syncthreads();
        if (c + 2 < CHUNKS) {
            int nb = buf + 2; if (nb >= 3) nb -= 3;
            issue_chunk(c + 2, nb);
        }

        const float* Bsp = Bsb[buf];
        const uint32_t asp_u = smem_u32(Asb[buf]);
#pragma unroll
        for (int s = 0; s < 4; s++) {
            uint32_t af[4][4], bf[4][2];
#pragma unroll
            for (int i = 0; i < 4; i++)
                ldsm_x4(af[i], asp_u + (uint32_t)(((alr + 16 * i) * ASTR) + 8 * s + alc) * 4u);
#pragma unroll
            for (int j = 0; j < 4; j++) {
                const float* bb = Bsp + (s * 8 + lc) * BSTR + wn * 32 + j * 8 + lr;
                bf[j][0] = __float_as_uint(bb[0]);
                bf[j][1] = __float_as_uint(bb[4 * BSTR]);
            }
#pragma unroll
            for (int i = 0; i < 4; i++)
#pragma unroll
                for (int j = 0; j < 4; j++)
                    mma_tf32(acc[i][j], af[i], bf[j]);
        }
        if (++buf >= 3) buf = 0;
    }

#pragma unroll
    for (int i = 0; i < 4; i++) {
#pragma unroll
        for (int j = 0; j < 4; j++) {
            float* cp0 = C + (size_t)(bm + wm * 64 + i * 16 + lr) * N
                           + bn + wn * 32 + j * 8 + 2 * lc;
            float* cp1 = cp0 + 8 * N;
            *(float2*)cp0 = make_float2(acc[i][j][0], acc[i][j][1]);
            *(float2*)cp1 = make_float2(acc[i][j][2], acc[i][j][3]);
        }
    }
}

__global__ __launch_bounds__(256, 2) void gemm_one(
    const float* __restrict__ A, const float* __restrict__ W,
    float* __restrict__ C, int M, int N, int K)
{
    extern __shared__ float sh[];
    gemm_body(A, W, C, M, N, K, sh);
}

__global__ __launch_bounds__(256, 2) void gemm_qkv(
    const float* __restrict__ A, int M, int N, int K)
{
    extern __shared__ float sh[];
    const int z = blockIdx.z;
    const float* W = (z == 0) ? g_wq : (z == 1) ? g_wk : g_wv;
    float* C       = (z == 0) ? g_q  : (z == 1) ? g_k  : g_v;
    gemm_body(A, W, C, M, N, K, sh);
}

// ---------------------------------------------------------------------------
// split_fused — rope+round Q/K (blocks < 8192), V transpose+split (rest).
// ---------------------------------------------------------------------------
#define ROPE_BLOCKS (ROWS * H_ * 32 / 256)   /* 8192 */
#define VT_BLOCKS   ((S_ / 64) * B_ * H_)    /* 1024 */

__global__ __launch_bounds__(256) void split_fused_kernel(
    const float* __restrict__ q, const float* __restrict__ k,
    const float* __restrict__ v)
{
    __shared__ float tile[64][65];
    const int bid = blockIdx.x;
    const int tid = threadIdx.x;

    if (bid < ROPE_BLOCKS) {
        int idx = bid * 256 + tid;
        int i   = idx & 31;
        int h   = (idx >> 5) & (H_ - 1);
        int row = idx >> 9;
        int pos = row & (S_ - 1);

        float c = g_cos[pos * 32 + i];
        float s = g_sin[pos * 32 + i];

        size_t base = (size_t)row * D_ + h * HD_ + i;
        float q1 = q[base], q2 = q[base + 32];
        float k1 = k[base], k2 = k[base + 32];
        g_qt[base]      = __uint_as_float(f2tf32(q1 * c - q2 * s));
        g_qt[base + 32] = __uint_as_float(f2tf32(q2 * c + q1 * s));
        g_kt[base]      = __uint_as_float(f2tf32(k1 * c - k2 * s));
        g_kt[base + 32] = __uint_as_float(f2tf32(k2 * c + k1 * s));
        return;
    }

    const int vb = bid - ROPE_BLOCKS;
    const int s0 = (vb & 31) * 64;
    const int bh = vb >> 5;
    const int b  = bh >> 4;
    const int h  = bh & 15;

    for (int t = tid; t < 64 * 16; t += 256) {
        int ss = t >> 4;
        int dd = (t & 15) << 2;
        float4 vv = *(const float4*)(v + (size_t)(b * S_ + s0 + ss) * D_ + h * 64 + dd);
        tile[ss][dd + 0] = vv.x;
        tile[ss][dd + 1] = vv.y;
        tile[ss][dd + 2] = vv.z;
        tile[ss][dd + 3] = vv.w;
    }
    __syncthreads();

    for (int t = tid; t < 64 * 32; t += 256) {
        int dd = t >> 5;
        int cp = t & 31;
        float a  = tile[2 * cp][dd];
        float bb = tile[2 * cp + 1][dd];
        uint32_t hi, lo;
        split_bf16x2(a, bb, hi, lo);
        size_t off = ((size_t)bh * 64 + dd) * (S_ / 2) + (s0 >> 1) + cp;
        g_vthi[off] = hi;
        g_vtlo[off] = lo;
    }
}

// ---------------------------------------------------------------------------
// Launch 4 (ncu-captured): causal flash attention.
// FA2 register softmax + LPT + 3-stage cp.async + ldmatrix (all verified).
// NEW: fine-grained causal skip in the two diagonal tiles — per-warp uniform
// bound plim = min(4, wid+1-4*(kt-2qt)) skips S p-pairs / PV s-steps whose
// columns are entirely masked (their P entries are exactly 0) -> bit-identical.
// ---------------------------------------------------------------------------
#define STG_F   (64 * KS + 2 * 64 * TSTR)        /* 8960 floats = 35840 B */
#define ATTN_SMEM (3 * STG_F * 4)                /* 107520 B */

__global__ __launch_bounds__(256, 2) void attn_kernel(float* __restrict__ Cg)
{
    extern __shared__ float sf[];

    const int tid  = threadIdx.x;
    const int wid  = tid >> 5;
    const int lane = tid & 31;
    const int lr   = lane >> 2;
    const int lc   = lane & 3;
    const int g    = lane >> 3;
    const int ri   = lane & 7;
    const int brow = ((g >> 1) << 3) + ri;   // + 16*p
    const int bcol = (g & 1) << 2;           // + 8*s
    // LPT: block 0..31 -> qt=15 (heaviest) ... 480..511 -> qt=0 (lightest)
    const int bid  = blockIdx.x;
    const int qt   = (S_ / 128 - 1) - (bid >> 5);
    const int bh   = bid & 31;
    const int b    = bh >> 4;
    const int h    = bh & 15;
    const int q0   = qt * 128;
    const int m0   = wid * 16;

    auto KT  = [&](int buf) -> float*    { return sf + buf * STG_F; };
    auto VHI = [&](int buf) -> uint32_t* { return (uint32_t*)(sf + buf * STG_F + 64 * KS); };
    auto VLO = [&](int buf) -> uint32_t* { return (uint32_t*)(sf + buf * STG_F + 64 * KS + 64 * TSTR); };

    // Q fragments (tf32 bits), loaded once
    uint32_t qf[8][4];
    {
        const float* qp0 = g_qt + (size_t)(b * S_ + q0 + m0 + lr) * D_ + h * 64;
        const float* qp1 = qp0 + 8 * D_;
#pragma unroll
        for (int s = 0; s < 8; s++) {
            qf[s][0] = __float_as_uint(qp0[8 * s + lc]);
            qf[s][1] = __float_as_uint(qp1[8 * s + lc]);
            qf[s][2] = __float_as_uint(qp0[8 * s + lc + 4]);
            qf[s][3] = __float_as_uint(qp1[8 * s + lc + 4]);
        }
    }

    float o[8][4];
#pragma unroll
    for (int j = 0; j < 8; j++)
#pragma unroll
        for (int t = 0; t < 4; t++) o[j][t] = 0.f;
    float mrow0 = -1e30f, mrow1 = -1e30f;
    float lrow0 = 0.f,    lrow1 = 0.f;

    const float scale = 0.125f;        // 1/sqrt(64)
    const int r0g = q0 + m0 + lr;
    const int r1g = r0g + 8;
    const int nkt = 2 * qt + 2;

    auto issue = [&](int kt, int buf) {
        const int k0 = kt * 64;
        if (tid < 128) {
            const int row  = tid >> 1;
            const int half = (tid & 1) * 32;
            const float* src = g_kt + (size_t)(b * S_ + k0 + row) * D_ + h * 64 + half;
            uint32_t dst = smem_u32(KT(buf) + row * KS + half);
#pragma unroll
            for (int f = 0; f < 8; f++)
                CP_ASYNC16(dst + f * 16, src + f * 4);
        } else {
            const int row = tid & 63;
            const uint32_t* src = ((tid < 192) ? g_vthi : g_vtlo)
                + ((size_t)bh * 64 + row) * (S_ / 2) + (k0 >> 1);
            uint32_t dst = smem_u32(((tid < 192) ? VHI(buf) : VLO(buf)) + row * TSTR);
#pragma unroll
            for (int f = 0; f < 8; f++)
                CP_ASYNC16(dst + f * 16, src + f * 4);
        }
        CP_COMMIT();
    };

    issue(0, 0);
    issue(1, 1);

    int buf = 0;
    for (int kt = 0; kt < nkt; kt++) {
        if (kt + 1 < nkt) { CP_WAIT(1); } else { CP_WAIT(0); }
        __syncthreads();
        if (kt + 2 < nkt) {
            int nb2 = buf + 2; if (nb2 >= 3) nb2 -= 3;
            issue(kt + 2, nb2);
        }

        const bool active = !(kt == 2 * qt + 1 && m0 < 64);
        if (active) {
            const uint32_t kt_u = smem_u32(KT(buf));
            const uint32_t vh_u = smem_u32(VHI(buf));
            const uint32_t vl_u = smem_u32(VLO(buf));
            const int k0 = kt * 64;
            const bool diag = (kt >= 2 * qt);
            // warp-uniform causal tile bound: p/s iterations >= plim touch only
            // fully-masked columns (P exactly 0) and are skipped.
            int plim = 4;
            if (diag) {
                plim = wid + 1 - 4 * (kt - 2 * qt);
                if (plim > 4) plim = 4;
            }

            // ---- S = Q @ K^T : 1x tf32 k8, B-frags via ldmatrix.x4 ----
            float sacc[8][4];
#pragma unroll
            for (int j = 0; j < 8; j++)
#pragma unroll
                for (int t = 0; t < 4; t++) sacc[j][t] = 0.f;

#pragma unroll
            for (int s = 0; s < 8; s++) {
#pragma unroll
                for (int p = 0; p < 4; p++) {
                    if (p < plim) {
                        uint32_t bq[4];
                        ldsm_x4(bq, kt_u + (uint32_t)((16 * p + brow) * KS + 8 * s + bcol) * 4u);
                        mma_tf32(sacc[2 * p],     qf[s], bq);
                        mma_tf32(sacc[2 * p + 1], qf[s], bq + 2);
                    }
                }
            }

            // ---- scale + causal mask + row max (in-register) ----
            float mx0 = -1e30f, mx1 = -1e30f;
#pragma unroll
            for (int j = 0; j < 8; j++) {
                const int c0 = k0 + 8 * j + 2 * lc;
                const int c1 = c0 + 1;
                float v0 = sacc[j][0] * scale;
                float v1 = sacc[j][1] * scale;
                float v2 = sacc[j][2] * scale;
                float v3 = sacc[j][3] * scale;
                if (diag) {
                    if (c0 > r0g) v0 = -1e30f;
                    if (c1 > r0g) v1 = -1e30f;
                    if (c0 > r1g) v2 = -1e30f;
                    if (c1 > r1g) v3 = -1e30f;
                }
                sacc[j][0] = v0; sacc[j][1] = v1;
                sacc[j][2] = v2; sacc[j][3] = v3;
                mx0 = fmaxf(mx0, fmaxf(v0, v1));
                mx1 = fmaxf(mx1, fmaxf(v2, v3));
            }
            mx0 = fmaxf(mx0, __shfl_xor_sync(0xffffffffu, mx0, 1));
            mx0 = fmaxf(mx0, __shfl_xor_sync(0xffffffffu, mx0, 2));
            mx1 = fmaxf(mx1, __shfl_xor_sync(0xffffffffu, mx1, 1));
            mx1 = fmaxf(mx1, __shfl_xor_sync(0xffffffffu, mx1, 2));

            const float mn0 = fmaxf(mrow0, mx0);
            const float mn1 = fmaxf(mrow1, mx1);
            const float a0  = __expf(mrow0 - mn0);
            const float a1  = __expf(mrow1 - mn1);
            mrow0 = mn0; mrow1 = mn1;

            float rs0 = 0.f, rs1 = 0.f;
#pragma unroll
            for (int j = 0; j < 8; j++) {
                sacc[j][0] = __expf(sacc[j][0] - mn0);
                sacc[j][1] = __expf(sacc[j][1] - mn0);
                sacc[j][2] = __expf(sacc[j][2] - mn1);
                sacc[j][3] = __expf(sacc[j][3] - mn1);
                rs0 += sacc[j][0] + sacc[j][1];
                rs1 += sacc[j][2] + sacc[j][3];
            }
            rs0 += __shfl_xor_sync(0xffffffffu, rs0, 1);
            rs0 += __shfl_xor_sync(0xffffffffu, rs0, 2);
            rs1 += __shfl_xor_sync(0xffffffffu, rs1, 1);
            rs1 += __shfl_xor_sync(0xffffffffu, rs1, 2);
            lrow0 = lrow0 * a0 + rs0;
            lrow1 = lrow1 * a1 + rs1;

#pragma unroll
            for (int j = 0; j < 8; j++) {
                o[j][0] *= a0; o[j][1] *= a0;
                o[j][2] *= a1; o[j][3] *= a1;
            }

            // ---- O += P @ V : 3x bf16 k16 (s-steps >= plim have P==0) ----
#pragma unroll
            for (int s = 0; s < 4; s++) {
                if (s < plim) {
                    uint32_t ah[4], al_[4];
                    split_bf16x2(sacc[2 * s][0],     sacc[2 * s][1],     ah[0], al_[0]);
                    split_bf16x2(sacc[2 * s][2],     sacc[2 * s][3],     ah[1], al_[1]);
                    split_bf16x2(sacc[2 * s + 1][0], sacc[2 * s + 1][1], ah[2], al_[2]);
                    split_bf16x2(sacc[2 * s + 1][2], sacc[2 * s + 1][3], ah[3], al_[3]);
#pragma unroll
                    for (int p = 0; p < 4; p++) {
                        uint32_t off = (uint32_t)((16 * p + brow) * TSTR + 8 * s + bcol) * 4u;
                        uint32_t vhq[4], vlq[4];
                        ldsm_x4(vhq, vh_u + off);
                        ldsm_x4(vlq, vl_u + off);
                        mma_bf16(o[2 * p], ah, vlq);
                        mma_bf16(o[2 * p], al_, vhq);
                        mma_bf16(o[2 * p], ah, vhq);
                        mma_bf16(o[2 * p + 1], ah, vlq + 2);
                        mma_bf16(o[2 * p + 1], al_, vhq + 2);
                        mma_bf16(o[2 * p + 1], ah, vhq + 2);
                    }
                }
            }
        }
        if (++buf >= 3) buf = 0;
    }

    // ---- normalize, round to tf32, store ----
    {
        const float i0 = 1.f / lrow0;
        const float i1 = 1.f / lrow1;
        float* op0 = Cg + (size_t)(b * S_ + r0g) * D_ + h * 64;
        float* op1 = op0 + 8 * D_;
#pragma unroll
        for (int j = 0; j < 8; j++) {
            *(float2*)(op0 + 8 * j + 2 * lc) = make_float2(
                __uint_as_float(f2tf32(o[j][0] * i0)),
                __uint_as_float(f2tf32(o[j][1] * i0)));
            *(float2*)(op1 + 8 * j + 2 * lc) = make_float2(
                __uint_as_float(f2tf32(o[j][2] * i1)),
                __uint_as_float(f2tf32(o[j][3] * i1)));
        }
    }
}

// ---------------------------------------------------------------------------
extern "C" void kernel_launch(void* const* d_in, const int* in_sizes, int n_in,
                              void* d_out, int out_size)
{
    const float* x  = (const float*)d_in[0];
    const float* Wq = (const float*)d_in[1];
    const float* Wk = (const float*)d_in[2];
    const float* Wv = (const float*)d_in[3];
    const float* Wo = (const float*)d_in[4];
    float* out = (float*)d_out;

    float *q, *k, *v, *ctx, *xr, *wo;
    cudaGetSymbolAddress((void**)&q,   g_q);
    cudaGetSymbolAddress((void**)&k,   g_k);
    cudaGetSymbolAddress((void**)&v,   g_v);
    cudaGetSymbolAddress((void**)&ctx, g_ctx);
    cudaGetSymbolAddress((void**)&xr,  g_x);
    cudaGetSymbolAddress((void**)&wo,  g_wo);

    cudaFuncSetAttribute(attn_kernel,
                         cudaFuncAttributeMaxDynamicSharedMemorySize, ATTN_SMEM);
    cudaFuncSetAttribute(gemm_one,
                         cudaFuncAttributeMaxDynamicSharedMemorySize, GEMM_SMEM);
    cudaFuncSetAttribute(gemm_qkv,
                         cudaFuncAttributeMaxDynamicSharedMemorySize, GEMM_SMEM);

    // 1: prep (x + weight rounding, rope tables) — single launch.
    prep_all_kernel<<<PREP_BLOCKS, 256>>>(x, Wq, Wk, Wv, Wo);
    // 2: fused QKV projections.
    gemm_qkv<<<dim3(D_ / 128, ROWS / 128, 3), 256, GEMM_SMEM>>>(xr, ROWS, D_, D_);
    // 3: rope+round Q/K and V transpose/split.
    split_fused_kernel<<<ROPE_BLOCKS + VT_BLOCKS, 256>>>(q, k, v);
    // 4: attention (ncu captures this launch).
    attn_kernel<<<(S_ / 128) * B_ * H_, 256, ATTN_SMEM>>>(ctx);
    // 5: output projection.
    gemm_one<<<dim3(D_ / 128, ROWS / 128), 256, GEMM_SMEM>>>(ctx, wo, out, ROWS, D_, D_);
}

// round 17
// speedup vs baseline: 1.0589x; 1.0589x over previous
#include <cuda_runtime.h>
#include <cuda_bf16.h>
#include <math.h>
#include <stdint.h>

#define B_    2
#define S_    2048
#define D_    1024
#define H_    16
#define HD_   64
#define ROWS  (B_ * S_)   /* 4096 */
#define TSTR  36          /* u32 stride of packed bf16 V smem tiles */
#define KS    68          /* float stride of fp32 K smem tile */

// Scratch (allocation-free rule: __device__ globals)
__device__ float g_q[ROWS * D_];
__device__ float g_k[ROWS * D_];
__device__ float g_v[ROWS * D_];
__device__ float g_ctx[ROWS * D_];
__device__ float g_x[ROWS * D_];
__device__ float g_wq[D_ * D_];   // tf32-rounded [K][N] (natural layout)
__device__ float g_wk[D_ * D_];
__device__ float g_wv[D_ * D_];
__device__ float g_wo[D_ * D_];
__device__ float g_cos[S_ * 32];
__device__ float g_sin[S_ * 32];
// attention operands: Q/K tf32-rounded fp32 (post-rope), V packed bf16 hi/lo
__device__ float g_qt[ROWS * D_];
__device__ float g_kt[ROWS * D_];
__device__ uint32_t g_vthi[B_ * H_ * HD_ * (S_ / 2)];
__device__ uint32_t g_vtlo[B_ * H_ * HD_ * (S_ / 2)];

// ---------------------------------------------------------------------------
// helpers (portable PTX, no 'a'-suffix features)
// ---------------------------------------------------------------------------
__device__ __forceinline__ uint32_t f2tf32(float x) {
    uint32_t r;
    asm("cvt.rna.tf32.f32 %0, %1;" : "=r"(r) : "f"(x));
    return r;
}

__device__ __forceinline__ void mma_tf32(float* d, const uint32_t* a,
                                         const uint32_t* b) {
    asm volatile(
        "mma.sync.aligned.m16n8k8.row.col.f32.tf32.tf32.f32 "
        "{%0,%1,%2,%3}, {%4,%5,%6,%7}, {%8,%9}, {%0,%1,%2,%3};"
        : "+f"(d[0]), "+f"(d[1]), "+f"(d[2]), "+f"(d[3])
        : "r"(a[0]), "r"(a[1]), "r"(a[2]), "r"(a[3]),
          "r"(b[0]), "r"(b[1]));
}

__device__ __forceinline__ void mma_bf16(float* d, const uint32_t* a,
                                         const uint32_t* b) {
    asm volatile(
        "mma.sync.aligned.m16n8k16.row.col.f32.bf16.bf16.f32 "
        "{%0,%1,%2,%3}, {%4,%5,%6,%7}, {%8,%9}, {%0,%1,%2,%3};"
        : "+f"(d[0]), "+f"(d[1]), "+f"(d[2]), "+f"(d[3])
        : "r"(a[0]), "r"(a[1]), "r"(a[2]), "r"(a[3]),
          "r"(b[0]), "r"(b[1]));
}

__device__ __forceinline__ void ldsm_x4(uint32_t* r, uint32_t a) {
    asm volatile(
        "ldmatrix.sync.aligned.m8n8.x4.shared.b16 {%0,%1,%2,%3}, [%4];"
        : "=r"(r[0]), "=r"(r[1]), "=r"(r[2]), "=r"(r[3]) : "r"(a));
}

__device__ __forceinline__ void split_bf16x2(float a, float b,
                                             uint32_t& hi, uint32_t& lo) {
    __nv_bfloat16 ha = __float2bfloat16_rn(a);
    __nv_bfloat16 hb = __float2bfloat16_rn(b);
    __nv_bfloat162 h; h.x = ha; h.y = hb;
    hi = *reinterpret_cast<uint32_t*>(&h);
    float ra = a - __bfloat162float(ha);
    float rb = b - __bfloat162float(hb);
    __nv_bfloat162 l = __floats2bfloat162_rn(ra, rb);
    lo = *reinterpret_cast<uint32_t*>(&l);
}

__device__ __forceinline__ uint32_t smem_u32(const void* p) {
    uint32_t a;
    asm("{ .reg .u64 t; cvta.to.shared.u64 t, %1; cvt.u32.u64 %0, t; }"
        : "=r"(a) : "l"(p));
    return a;
}
#define CP_ASYNC16(dst_u32, src_ptr) \
    asm volatile("cp.async.cg.shared.global [%0], [%1], 16;" \
                 :: "r"(dst_u32), "l"(src_ptr))
#define CP_COMMIT() asm volatile("cp.async.commit_group;" ::: "memory")
#define CP_WAIT(N)  asm volatile("cp.async.wait_group %0;" :: "n"(N) : "memory")

// ---------------------------------------------------------------------------
// Launch 1: prep_all — rope tables FIRST (FP64-heavy blocks start in wave 1
// and overlap the bandwidth-bound rounding bulk), then x + 4 weights rounding.
// ---------------------------------------------------------------------------
#define XBLK   (ROWS * D_ / 4 / 256)   /* 4096 */
#define WBLK   (D_ * D_ / 4 / 256)     /* 1024 */
#define RTBLK  (S_ * 32 / 256)         /* 256 */
#define PREP_BLOCKS (RTBLK + XBLK + 4 * WBLK)

__global__ void prep_all_kernel(
    const float* __restrict__ x,
    const float* __restrict__ Wq, const float* __restrict__ Wk,
    const float* __restrict__ Wv, const float* __restrict__ Wo)
{
    int bid = blockIdx.x;
    if (bid < RTBLK) {
        // rope tables (FP64 trig) — scheduled first
        int idx = bid * 256 + threadIdx.x;
        int i = idx & 31, pos = idx >> 5;
        double invf_d = exp(-log(10000.0) * (double)(2 * i) / (double)HD_);
        float ang = (float)pos * (float)invf_d;
        double sd, cd;
        sincos((double)ang, &sd, &cd);
        g_cos[pos * 32 + i] = (float)cd;
        g_sin[pos * 32 + i] = (float)sd;
        return;
    }
    bid -= RTBLK;
    const float* s;
    float* d;
    int i;
    if (bid < XBLK) {
        s = x; d = g_x; i = (bid * 256 + threadIdx.x) * 4;
    } else {
        int z  = (bid - XBLK) / WBLK;
        int lb = (bid - XBLK) % WBLK;
        s = (z == 0) ? Wq : (z == 1) ? Wk : (z == 2) ? Wv : Wo;
        d = (z == 0) ? g_wq : (z == 1) ? g_wk : (z == 2) ? g_wv : g_wo;
        i = (lb * 256 + threadIdx.x) * 4;
    }
    float4 v = *(const float4*)(s + i);
    v.x = __uint_as_float(f2tf32(v.x));
    v.y = __uint_as_float(f2tf32(v.y));
    v.z = __uint_as_float(f2tf32(v.z));
    v.w = __uint_as_float(f2tf32(v.w));
    *(float4*)(d + i) = v;
}

// ---------------------------------------------------------------------------
// HMMA tf32 GEMM body — EXACT round-14 configuration (best measured):
// 3-stage cp.async, ONE barrier per chunk, 2 CTAs/SM, A-frags via ldmatrix,
// B [k][n] scalar fragment loads. ASTR 40 / BSTR 136.
// ---------------------------------------------------------------------------
#define ASTR 40
#define BSTR 136
#define AS_F (128 * ASTR)
#define BS_F (32 * BSTR)
#define GEMM_SMEM (3 * (AS_F + BS_F) * 4)   /* 113664 B */

__device__ __forceinline__ void gemm_body(
    const float* __restrict__ A, const float* __restrict__ W,
    float* __restrict__ C, int M, int N, int K, float* sh)
{
    float* Asb[3] = {sh, sh + AS_F, sh + 2 * AS_F};
    float* Bsb[3] = {sh + 3 * AS_F, sh + 3 * AS_F + BS_F, sh + 3 * AS_F + 2 * BS_F};

    const int tid  = threadIdx.x;
    const int wid  = tid >> 5;
    const int lane = tid & 31;
    const int bm   = blockIdx.y * 128;
    const int bn   = blockIdx.x * 128;
    const int wm   = wid >> 2;
    const int wn   = wid & 3;
    const int lr   = lane >> 2;
    const int lc   = lane & 3;
    const int g    = lane >> 3;
    const int ri   = lane & 7;
    const int alr  = wm * 64 + ((g & 1) << 3) + ri;  // + 16*i
    const int alc  = (g >> 1) << 2;                  // + 8*s

    const int a_r  = tid >> 1;
    const int a_c  = (tid & 1) * 16;
    const int b_r  = tid >> 3;
    const int b_c  = (tid & 7) * 4;

    const float* Arow = A + (size_t)(bm + a_r) * K + a_c;
    const float* Wrow0 = W + (size_t)b_r * N + bn + b_c;

    float acc[4][4][4];
#pragma unroll
    for (int i = 0; i < 4; i++)
#pragma unroll
        for (int j = 0; j < 4; j++)
#pragma unroll
            for (int t = 0; t < 4; t++) acc[i][j][t] = 0.f;

    auto issue_chunk = [&](int c, int buf) {
        uint32_t ad = smem_u32(Asb[buf] + a_r * ASTR + a_c);
        const float* ap = Arow + c * 32;
#pragma unroll
        for (int f = 0; f < 4; f++)
            CP_ASYNC16(ad + f * 16, ap + f * 4);
        uint32_t bd = smem_u32(Bsb[buf] + b_r * BSTR + b_c);
        const float* bp = Wrow0 + (size_t)(c * 32) * N;
#pragma unroll
        for (int f = 0; f < 4; f++)
            CP_ASYNC16(bd + f * 128, bp + f * 32);
        CP_COMMIT();
    };

    const int CHUNKS = K / 32;
    issue_chunk(0, 0);
    issue_chunk(1, 1);

    int buf = 0;
    for (int c = 0; c < CHUNKS; c++) {
        if (c + 1 < CHUNKS) { CP_WAIT(1); } else { CP_WAIT(0); }
        __syncthreads();
        if (c + 2 < CHUNKS) {
            int nb = buf + 2; if (nb >= 3) nb -= 3;
            issue_chunk(c + 2, nb);
        }

        const float* Bsp = Bsb[buf];
        const uint32_t asp_u = smem_u32(Asb[buf]);
#pragma unroll
        for (int s = 0; s < 4; s++) {
            uint32_t af[4][4], bf[4][2];
#pragma unroll
            for (int i = 0; i < 4; i++)
                ldsm_x4(af[i], asp_u + (uint32_t)(((alr + 16 * i) * ASTR) + 8 * s + alc) * 4u);
#pragma unroll
            for (int j = 0; j < 4; j++) {
                const float* bb = Bsp + (s * 8 + lc) * BSTR + wn * 32 + j * 8 + lr;
                bf[j][0] = __float_as_uint(bb[0]);
                bf[j][1] = __float_as_uint(bb[4 * BSTR]);
            }
#pragma unroll
            for (int i = 0; i < 4; i++)
#pragma unroll
                for (int j = 0; j < 4; j++)
                    mma_tf32(acc[i][j], af[i], bf[j]);
        }
        if (++buf >= 3) buf = 0;
    }

#pragma unroll
    for (int i = 0; i < 4; i++) {
#pragma unroll
        for (int j = 0; j < 4; j++) {
            float* cp0 = C + (size_t)(bm + wm * 64 + i * 16 + lr) * N
                           + bn + wn * 32 + j * 8 + 2 * lc;
            float* cp1 = cp0 + 8 * N;
            *(float2*)cp0 = make_float2(acc[i][j][0], acc[i][j][1]);
            *(float2*)cp1 = make_float2(acc[i][j][2], acc[i][j][3]);
        }
    }
}

__global__ __launch_bounds__(256, 2) void gemm_one(
    const float* __restrict__ A, const float* __restrict__ W,
    float* __restrict__ C, int M, int N, int K)
{
    extern __shared__ float sh[];
    gemm_body(A, W, C, M, N, K, sh);
}

__global__ __launch_bounds__(256, 2) void gemm_qkv(
    const float* __restrict__ A, int M, int N, int K)
{
    extern __shared__ float sh[];
    const int z = blockIdx.z;
    const float* W = (z == 0) ? g_wq : (z == 1) ? g_wk : g_wv;
    float* C       = (z == 0) ? g_q  : (z == 1) ? g_k  : g_v;
    gemm_body(A, W, C, M, N, K, sh);
}

// ---------------------------------------------------------------------------
// split_fused — rope+round Q/K (blocks < 8192), V transpose+split (rest).
// ---------------------------------------------------------------------------
#define ROPE_BLOCKS (ROWS * H_ * 32 / 256)   /* 8192 */
#define VT_BLOCKS   ((S_ / 64) * B_ * H_)    /* 1024 */

__global__ __launch_bounds__(256) void split_fused_kernel(
    const float* __restrict__ q, const float* __restrict__ k,
    const float* __restrict__ v)
{
    __shared__ float tile[64][65];
    const int bid = blockIdx.x;
    const int tid = threadIdx.x;

    if (bid < ROPE_BLOCKS) {
        int idx = bid * 256 + tid;
        int i   = idx & 31;
        int h   = (idx >> 5) & (H_ - 1);
        int row = idx >> 9;
        int pos = row & (S_ - 1);

        float c = g_cos[pos * 32 + i];
        float s = g_sin[pos * 32 + i];

        size_t base = (size_t)row * D_ + h * HD_ + i;
        float q1 = q[base], q2 = q[base + 32];
        float k1 = k[base], k2 = k[base + 32];
        g_qt[base]      = __uint_as_float(f2tf32(q1 * c - q2 * s));
        g_qt[base + 32] = __uint_as_float(f2tf32(q2 * c + q1 * s));
        g_kt[base]      = __uint_as_float(f2tf32(k1 * c - k2 * s));
        g_kt[base + 32] = __uint_as_float(f2tf32(k2 * c + k1 * s));
        return;
    }

    const int vb = bid - ROPE_BLOCKS;
    const int s0 = (vb & 31) * 64;
    const int bh = vb >> 5;
    const int b  = bh >> 4;
    const int h  = bh & 15;

    for (int t = tid; t < 64 * 16; t += 256) {
        int ss = t >> 4;
        int dd = (t & 15) << 2;
        float4 vv = *(const float4*)(v + (size_t)(b * S_ + s0 + ss) * D_ + h * 64 + dd);
        tile[ss][dd + 0] = vv.x;
        tile[ss][dd + 1] = vv.y;
        tile[ss][dd + 2] = vv.z;
        tile[ss][dd + 3] = vv.w;
    }
    __syncthreads();

    for (int t = tid; t < 64 * 32; t += 256) {
        int dd = t >> 5;
        int cp = t & 31;
        float a  = tile[2 * cp][dd];
        float bb = tile[2 * cp + 1][dd];
        uint32_t hi, lo;
        split_bf16x2(a, bb, hi, lo);
        size_t off = ((size_t)bh * 64 + dd) * (S_ / 2) + (s0 >> 1) + cp;
        g_vthi[off] = hi;
        g_vtlo[off] = lo;
    }
}

// ---------------------------------------------------------------------------
// Causal flash attention — EXACT round-14 code (best measured):
// FA2 register softmax + LPT + 3-stage cp.async + ldmatrix. NO plim skip.
// ---------------------------------------------------------------------------
#define STG_F   (64 * KS + 2 * 64 * TSTR)        /* 8960 floats = 35840 B */
#define ATTN_SMEM (3 * STG_F * 4)                /* 107520 B */

__global__ __launch_bounds__(256, 2) void attn_kernel(float* __restrict__ Cg)
{
    extern __shared__ float sf[];

    const int tid  = threadIdx.x;
    const int wid  = tid >> 5;
    const int lane = tid & 31;
    const int lr   = lane >> 2;
    const int lc   = lane & 3;
    const int g    = lane >> 3;
    const int ri   = lane & 7;
    const int brow = ((g >> 1) << 3) + ri;   // + 16*p
    const int bcol = (g & 1) << 2;           // + 8*s
    // LPT: block 0..31 -> qt=15 (heaviest) ... 480..511 -> qt=0 (lightest)
    const int bid  = blockIdx.x;
    const int qt   = (S_ / 128 - 1) - (bid >> 5);
    const int bh   = bid & 31;
    const int b    = bh >> 4;
    const int h    = bh & 15;
    const int q0   = qt * 128;
    const int m0   = wid * 16;

    auto KT  = [&](int buf) -> float*    { return sf + buf * STG_F; };
    auto VHI = [&](int buf) -> uint32_t* { return (uint32_t*)(sf + buf * STG_F + 64 * KS); };
    auto VLO = [&](int buf) -> uint32_t* { return (uint32_t*)(sf + buf * STG_F + 64 * KS + 64 * TSTR); };

    // Q fragments (tf32 bits), loaded once
    uint32_t qf[8][4];
    {
        const float* qp0 = g_qt + (size_t)(b * S_ + q0 + m0 + lr) * D_ + h * 64;
        const float* qp1 = qp0 + 8 * D_;
#pragma unroll
        for (int s = 0; s < 8; s++) {
            qf[s][0] = __float_as_uint(qp0[8 * s + lc]);
            qf[s][1] = __float_as_uint(qp1[8 * s + lc]);
            qf[s][2] = __float_as_uint(qp0[8 * s + lc + 4]);
            qf[s][3] = __float_as_uint(qp1[8 * s + lc + 4]);
        }
    }

    float o[8][4];
#pragma unroll
    for (int j = 0; j < 8; j++)
#pragma unroll
        for (int t = 0; t < 4; t++) o[j][t] = 0.f;
    float mrow0 = -1e30f, mrow1 = -1e30f;
    float lrow0 = 0.f,    lrow1 = 0.f;

    const float scale = 0.125f;        // 1/sqrt(64)
    const int r0g = q0 + m0 + lr;
    const int r1g = r0g + 8;
    const int nkt = 2 * qt + 2;

    auto issue = [&](int kt, int buf) {
        const int k0 = kt * 64;
        if (tid < 128) {
            const int row  = tid >> 1;
            const int half = (tid & 1) * 32;
            const float* src = g_kt + (size_t)(b * S_ + k0 + row) * D_ + h * 64 + half;
            uint32_t dst = smem_u32(KT(buf) + row * KS + half);
#pragma unroll
            for (int f = 0; f < 8; f++)
                CP_ASYNC16(dst + f * 16, src + f * 4);
        } else {
            const int row = tid & 63;
            const uint32_t* src = ((tid < 192) ? g_vthi : g_vtlo)
                + ((size_t)bh * 64 + row) * (S_ / 2) + (k0 >> 1);
            uint32_t dst = smem_u32(((tid < 192) ? VHI(buf) : VLO(buf)) + row * TSTR);
#pragma unroll
            for (int f = 0; f < 8; f++)
                CP_ASYNC16(dst + f * 16, src + f * 4);
        }
        CP_COMMIT();
    };

    issue(0, 0);
    issue(1, 1);

    int buf = 0;
    for (int kt = 0; kt < nkt; kt++) {
        if (kt + 1 < nkt) { CP_WAIT(1); } else { CP_WAIT(0); }
        __syncthreads();
        if (kt + 2 < nkt) {
            int nb2 = buf + 2; if (nb2 >= 3) nb2 -= 3;
            issue(kt + 2, nb2);
        }

        const bool active = !(kt == 2 * qt + 1 && m0 < 64);
        if (active) {
            const uint32_t kt_u = smem_u32(KT(buf));
            const uint32_t vh_u = smem_u32(VHI(buf));
            const uint32_t vl_u = smem_u32(VLO(buf));
            const int k0 = kt * 64;

            // ---- S = Q @ K^T : 1x tf32 k8, B-frags via ldmatrix.x4 ----
            float sacc[8][4];
#pragma unroll
            for (int j = 0; j < 8; j++)
#pragma unroll
                for (int t = 0; t < 4; t++) sacc[j][t] = 0.f;

#pragma unroll
            for (int s = 0; s < 8; s++) {
#pragma unroll
                for (int p = 0; p < 4; p++) {
                    uint32_t bq[4];
                    ldsm_x4(bq, kt_u + (uint32_t)((16 * p + brow) * KS + 8 * s + bcol) * 4u);
                    mma_tf32(sacc[2 * p],     qf[s], bq);
                    mma_tf32(sacc[2 * p + 1], qf[s], bq + 2);
                }
            }

            // ---- scale + causal mask + row max (in-register) ----
            const bool diag = (kt >= 2 * qt);
            float mx0 = -1e30f, mx1 = -1e30f;
#pragma unroll
            for (int j = 0; j < 8; j++) {
                const int c0 = k0 + 8 * j + 2 * lc;
                const int c1 = c0 + 1;
                float v0 = sacc[j][0] * scale;
                float v1 = sacc[j][1] * scale;
                float v2 = sacc[j][2] * scale;
                float v3 = sacc[j][3] * scale;
                if (diag) {
                    if (c0 > r0g) v0 = -1e30f;
                    if (c1 > r0g) v1 = -1e30f;
                    if (c0 > r1g) v2 = -1e30f;
                    if (c1 > r1g) v3 = -1e30f;
                }
                sacc[j][0] = v0; sacc[j][1] = v1;
                sacc[j][2] = v2; sacc[j][3] = v3;
                mx0 = fmaxf(mx0, fmaxf(v0, v1));
                mx1 = fmaxf(mx1, fmaxf(v2, v3));
            }
            mx0 = fmaxf(mx0, __shfl_xor_sync(0xffffffffu, mx0, 1));
            mx0 = fmaxf(mx0, __shfl_xor_sync(0xffffffffu, mx0, 2));
            mx1 = fmaxf(mx1, __shfl_xor_sync(0xffffffffu, mx1, 1));
            mx1 = fmaxf(mx1, __shfl_xor_sync(0xffffffffu, mx1, 2));

            const float mn0 = fmaxf(mrow0, mx0);
            const float mn1 = fmaxf(mrow1, mx1);
            const float a0  = __expf(mrow0 - mn0);
            const float a1  = __expf(mrow1 - mn1);
            mrow0 = mn0; mrow1 = mn1;

            float rs0 = 0.f, rs1 = 0.f;
#pragma unroll
            for (int j = 0; j < 8; j++) {
                sacc[j][0] = __expf(sacc[j][0] - mn0);
                sacc[j][1] = __expf(sacc[j][1] - mn0);
                sacc[j][2] = __expf(sacc[j][2] - mn1);
                sacc[j][3] = __expf(sacc[j][3] - mn1);
                rs0 += sacc[j][0] + sacc[j][1];
                rs1 += sacc[j][2] + sacc[j][3];
            }
            rs0 += __shfl_xor_sync(0xffffffffu, rs0, 1);
            rs0 += __shfl_xor_sync(0xffffffffu, rs0, 2);
            rs1 += __shfl_xor_sync(0xffffffffu, rs1, 1);
            rs1 += __shfl_xor_sync(0xffffffffu, rs1, 2);
            lrow0 = lrow0 * a0 + rs0;
            lrow1 = lrow1 * a1 + rs1;

#pragma unroll
            for (int j = 0; j < 8; j++) {
                o[j][0] *= a0; o[j][1] *= a0;
                o[j][2] *= a1; o[j][3] *= a1;
            }

            // ---- O += P @ V : 3x bf16 k16, V-frags via ldmatrix.x4 ----
#pragma unroll
            for (int s = 0; s < 4; s++) {
                uint32_t ah[4], al_[4];
                split_bf16x2(sacc[2 * s][0],     sacc[2 * s][1],     ah[0], al_[0]);
                split_bf16x2(sacc[2 * s][2],     sacc[2 * s][3],     ah[1], al_[1]);
                split_bf16x2(sacc[2 * s + 1][0], sacc[2 * s + 1][1], ah[2], al_[2]);
                split_bf16x2(sacc[2 * s + 1][2], sacc[2 * s + 1][3], ah[3], al_[3]);
#pragma unroll
                for (int p = 0; p < 4; p++) {
                    uint32_t off = (uint32_t)((16 * p + brow) * TSTR + 8 * s + bcol) * 4u;
                    uint32_t vhq[4], vlq[4];
                    ldsm_x4(vhq, vh_u + off);
                    ldsm_x4(vlq, vl_u + off);
                    mma_bf16(o[2 * p], ah, vlq);
                    mma_bf16(o[2 * p], al_, vhq);
                    mma_bf16(o[2 * p], ah, vhq);
                    mma_bf16(o[2 * p + 1], ah, vlq + 2);
                    mma_bf16(o[2 * p + 1], al_, vhq + 2);
                    mma_bf16(o[2 * p + 1], ah, vhq + 2);
                }
            }
        }
        if (++buf >= 3) buf = 0;
    }

    // ---- normalize, round to tf32, store ----
    {
        const float i0 = 1.f / lrow0;
        const float i1 = 1.f / lrow1;
        float* op0 = Cg + (size_t)(b * S_ + r0g) * D_ + h * 64;
        float* op1 = op0 + 8 * D_;
#pragma unroll
        for (int j = 0; j < 8; j++) {
            *(float2*)(op0 + 8 * j + 2 * lc) = make_float2(
                __uint_as_float(f2tf32(o[j][0] * i0)),
                __uint_as_float(f2tf32(o[j][1] * i0)));
            *(float2*)(op1 + 8 * j + 2 * lc) = make_float2(
                __uint_as_float(f2tf32(o[j][2] * i1)),
                __uint_as_float(f2tf32(o[j][3] * i1)));
        }
    }
}

// ---------------------------------------------------------------------------
extern "C" void kernel_launch(void* const* d_in, const int* in_sizes, int n_in,
                              void* d_out, int out_size)
{
    const float* x  = (const float*)d_in[0];
    const float* Wq = (const float*)d_in[1];
    const float* Wk = (const float*)d_in[2];
    const float* Wv = (const float*)d_in[3];
    const float* Wo = (const float*)d_in[4];
    float* out = (float*)d_out;

    float *q, *k, *v, *ctx, *xr, *wo;
    cudaGetSymbolAddress((void**)&q,   g_q);
    cudaGetSymbolAddress((void**)&k,   g_k);
    cudaGetSymbolAddress((void**)&v,   g_v);
    cudaGetSymbolAddress((void**)&ctx, g_ctx);
    cudaGetSymbolAddress((void**)&xr,  g_x);
    cudaGetSymbolAddress((void**)&wo,  g_wo);

    cudaFuncSetAttribute(attn_kernel,
                         cudaFuncAttributeMaxDynamicSharedMemorySize, ATTN_SMEM);
    cudaFuncSetAttribute(gemm_one,
                         cudaFuncAttributeMaxDynamicSharedMemorySize, GEMM_SMEM);
    cudaFuncSetAttribute(gemm_qkv,
                         cudaFuncAttributeMaxDynamicSharedMemorySize, GEMM_SMEM);

    // 1: prep (rope tables first, then x + weight rounding) — single launch.
    prep_all_kernel<<<PREP_BLOCKS, 256>>>(x, Wq, Wk, Wv, Wo);
    // 2: fused QKV projections.
    gemm_qkv<<<dim3(D_ / 128, ROWS / 128, 3), 256, GEMM_SMEM>>>(xr, ROWS, D_, D_);
    // 3: rope+round Q/K and V transpose/split.
    split_fused_kernel<<<ROPE_BLOCKS + VT_BLOCKS, 256>>>(q, k, v);
    // 4: attention.
    attn_kernel<<<(S_ / 128) * B_ * H_, 256, ATTN_SMEM>>>(ctx);
    // 5: output projection.
    gemm_one<<<dim3(D_ / 128, ROWS / 128), 256, GEMM_SMEM>>>(ctx, wo, out, ROWS, D_, D_);
}